// round 11
// baseline (speedup 1.0000x reference)
#include <cuda_runtime.h>
#include <cuda_fp16.h>
#include <cstdint>

#define N_TOK 32768
#define DIM 768
#define NE 64
#define NH 256
#define NH2 128
#define NO 2

// ---------------- scratch (no allocations allowed) ----------------
__device__ int g_hist[NE];
__device__ int g_tokidx[NE * 1024];  // strided per-head segments
__device__ int g_ntiles;
__device__ int g_next;
__device__ int g_p64;
#define MAXT 512
__device__ int g_tile_head[MAXT];
__device__ int g_tile_start[MAXT];
__device__ int g_tile_rows[MAXT];
// fp16 normalized activations + folded weights
__device__ __half g_Xh[(size_t)N_TOK * DIM];     // xhat, fp16
__device__ __half g_W1h[(size_t)NE * NH * DIM];  // (diag(gamma)*W1)^T per head
__device__ __half g_W2h[(size_t)NE * NH2 * NH];  // W2^T per head
__device__ float g_b1p[NE * NH];                 // beta @ W1
__device__ __half g_zero[64];                    // zero row source for padding

// ---------------- helpers ----------------
__device__ __forceinline__ void mma_f16(float* d, const uint32_t* a, const uint32_t* b) {
    asm volatile(
        "mma.sync.aligned.m16n8k16.row.col.f32.f16.f16.f32 "
        "{%0,%1,%2,%3}, {%4,%5,%6,%7}, {%8,%9}, {%0,%1,%2,%3};\n"
        : "+f"(d[0]), "+f"(d[1]), "+f"(d[2]), "+f"(d[3])
        : "r"(a[0]), "r"(a[1]), "r"(a[2]), "r"(a[3]), "r"(b[0]), "r"(b[1]));
}

__device__ __forceinline__ void cp16(uint32_t dst_smem, const void* src) {
    asm volatile("cp.async.cg.shared.global [%0], [%1], 16;\n" ::"r"(dst_smem), "l"(src));
}
#define CP_COMMIT() asm volatile("cp.async.commit_group;\n" ::: "memory")
#define CP_WAIT0() asm volatile("cp.async.wait_group 0;\n" ::: "memory")

__device__ __forceinline__ int get_prop(const void* props, int t, int p64) {
    int v;
    if (p64) v = (int)((const long long*)props)[t];
    else     v = ((const int*)props)[t];
    return v & (NE - 1);
}

__device__ __forceinline__ uint32_t h2u(__half2 h) {
    uint32_t u;
    *(__half2*)&u = h;
    return u;
}

// ---------------- L1: k_prep — reset + W1 fold/convert/transpose + W2 convert/transpose ----
// grid (12, 64): blockIdx.x<8 -> W1 n-tile, >=8 -> W2 n-tile; blockIdx.y = head e
__global__ void k_prep(const float* __restrict__ W1, const float* __restrict__ W2,
                       const float* __restrict__ ln_g, const float* __restrict__ ln_b,
                       const unsigned* __restrict__ pw) {
    __shared__ float s[32][33];
    __shared__ float lg[32], lb[32];
    const int tx = threadIdx.x, ty = threadIdx.y;
    const int role = blockIdx.x;
    const int e = blockIdx.y;

    if (role == 0 && e == 0) {  // reset duties (once)
        int tid = ty * 32 + tx;
        if (tid < NE) g_hist[tid] = 0;
        if (tid >= 64 && tid < 96) ((uint32_t*)g_zero)[tid - 64] = 0u;
        if (ty == 7) {  // p64 detection warp
            int odd_nonzero = 0;
#pragma unroll
            for (int i = 0; i < 4; i++)
                if (pw[2 * (tx + 32 * i) + 1] != 0u) odd_nonzero = 1;
            unsigned b = __ballot_sync(0xFFFFFFFFu, odd_nonzero);
            if (tx == 0) g_p64 = (b == 0u) ? 1 : 0;
        }
    }

    if (role < 8) {  // W1: fold gamma, transpose, fp16; accumulate beta@W1
        const int n0 = role * 32;
        const float* src = W1 + (size_t)e * DIM * NH;
        float bacc = 0.f;
        for (int k0 = 0; k0 < DIM; k0 += 32) {
            __syncthreads();
#pragma unroll
            for (int d = 0; d < 4; d++)
                s[ty + 8 * d][tx] = src[(size_t)(k0 + ty + 8 * d) * NH + n0 + tx];
            if (ty == 0) {
                lg[tx] = ln_g[(size_t)e * DIM + k0 + tx];
                lb[tx] = ln_b[(size_t)e * DIM + k0 + tx];
            }
            __syncthreads();
            if (tx < 16) {
#pragma unroll
                for (int d = 0; d < 4; d++) {
                    int n = n0 + ty + 8 * d;
                    __half2 h = __floats2half2_rn(s[2 * tx][ty + 8 * d] * lg[2 * tx],
                                                  s[2 * tx + 1][ty + 8 * d] * lg[2 * tx + 1]);
                    ((__half2*)(g_W1h + (size_t)e * NH * DIM + (size_t)n * DIM + k0))[tx] = h;
                }
            }
            if (ty == 1) {
#pragma unroll
                for (int kk = 0; kk < 32; kk++) bacc += lb[kk] * s[kk][tx];
            }
        }
        if (ty == 1) g_b1p[e * NH + n0 + tx] = bacc;
    } else {  // W2: transpose + fp16
        const int n0 = (role - 8) * 32;
        const float* src = W2 + (size_t)e * NH * NH2;
        for (int k0 = 0; k0 < NH; k0 += 32) {
            __syncthreads();
#pragma unroll
            for (int d = 0; d < 4; d++)
                s[ty + 8 * d][tx] = src[(size_t)(k0 + ty + 8 * d) * NH2 + n0 + tx];
            __syncthreads();
            if (tx < 16) {
#pragma unroll
                for (int d = 0; d < 4; d++) {
                    int n = n0 + ty + 8 * d;
                    __half2 h = __floats2half2_rn(s[2 * tx][ty + 8 * d], s[2 * tx + 1][ty + 8 * d]);
                    ((__half2*)(g_W2h + (size_t)e * NH2 * NH + (size_t)n * NH + k0))[tx] = h;
                }
            }
        }
    }
}

// ---------------- L2: k_stats — LN -> xhat fp16 + fused scatter + masked zero ----------------
__global__ void k_stats(const float* __restrict__ hidden,
                        const void* __restrict__ props,
                        const float* __restrict__ mask,
                        float* __restrict__ out) {
    int token = blockIdx.x * 8 + (threadIdx.x >> 5);
    int lane = threadIdx.x & 31;
    const float4* xr = (const float4*)(hidden + (size_t)token * DIM);
    float4 v[6];
    float s = 0.f, q = 0.f;
#pragma unroll
    for (int i = 0; i < 6; i++) {
        v[i] = xr[lane + 32 * i];
        s += v[i].x + v[i].y + v[i].z + v[i].w;
        q += v[i].x * v[i].x + v[i].y * v[i].y + v[i].z * v[i].z + v[i].w * v[i].w;
    }
#pragma unroll
    for (int o = 16; o > 0; o >>= 1) {
        s += __shfl_xor_sync(0xFFFFFFFFu, s, o);
        q += __shfl_xor_sync(0xFFFFFFFFu, q, o);
    }
    float mu = s * (1.f / DIM);
    float var = q * (1.f / DIM) - mu * mu;
    float rs = rsqrtf(var + 1e-5f);
    uint2* xd = (uint2*)(g_Xh + (size_t)token * DIM);
#pragma unroll
    for (int i = 0; i < 6; i++) {
        uint2 u;
        u.x = h2u(__floats2half2_rn((v[i].x - mu) * rs, (v[i].y - mu) * rs));
        u.y = h2u(__floats2half2_rn((v[i].z - mu) * rs, (v[i].w - mu) * rs));
        xd[lane + 32 * i] = u;
    }
    if (lane == 0) {
        float m = mask[token];
        if (m > 0.f) {
            int p = get_prop(props, token, g_p64);
            int rank = atomicAdd(&g_hist[p], 1);  // rank doubles as scatter position
            if (rank < 1024) g_tokidx[p * 1024 + rank] = token;
        } else {
            out[token * 2 + 0] = 0.f;
            out[token * 2 + 1] = 0.f;
        }
    }
}

// ---------------- L3: k_plan — tiles over strided per-head segments ----------------
__global__ void k_plan() {
    if (threadIdx.x == 0) {
        int nt = 0;
        for (int e = 0; e < NE; e++) {
            int c = min(g_hist[e], 1024);
            for (int s = 0; s < c && nt < MAXT; s += 128) {
                g_tile_head[nt] = e;
                g_tile_start[nt] = e * 1024 + s;
                g_tile_rows[nt] = min(128, c - s);
                nt++;
            }
        }
        g_ntiles = nt;
        g_next = 0;
    }
}

// ---------------- L4: k_main — fp16 mma.sync grouped adapter (persistent CTAs) ----------------
#define LDAW 20    // A tile [128 rows][16 words + pad4]
#define LDWW 20    // W tile [n rows][16 words + pad4]
#define LDH1W 132  // H1 [128][128 words + pad4]
#define LDH2F 132  // H2 f32 [128][128 + pad4]

#define OFF_A0 0u
#define OFF_A1 10240u
#define OFF_W 20480u       // 2 x 20480
#define OFF_H1 61440u      // 67584 (half words; f32 H2 aliases after GEMM2)
#define OFF_H2 61440u
#define OFF_B1 129024u
#define OFF_B2 130048u
#define OFF_W3T 130560u
#define OFF_TOK 131584u
#define SMEM_BYTES 132096u

__global__ __launch_bounds__(512) void k_main(
    const float* __restrict__ base,
    const float* __restrict__ b1, const float* __restrict__ b2,
    const float* __restrict__ W3, const float* __restrict__ b3,
    float* __restrict__ out)
{
    extern __shared__ char smem[];
    const uint32_t sb = (uint32_t)__cvta_generic_to_shared(smem);
    float* sB1 = (float*)(smem + OFF_B1);
    float* sB2 = (float*)(smem + OFF_B2);
    float* sW3T = (float*)(smem + OFF_W3T);
    int* sTok = (int*)(smem + OFF_TOK);
    uint32_t* sH1w = (uint32_t*)(smem + OFF_H1);
    float* sH2 = (float*)(smem + OFF_H2);
    __shared__ int s_tile;

    const int tid = threadIdx.x;
    const int wid = tid >> 5;
    const int lane = tid & 31;
    const int g = lane >> 2;
    const int t4 = lane & 3;
    const int arow = tid >> 2;
    const int akc = tid & 3;
    const int wm = wid >> 2;
    const int wn = wid & 3;

#define CP_XW1(k0, buf)                                                        \
    {                                                                          \
        const __half* xsrc = (tokr >= 0) ? g_Xh + (size_t)tokr * DIM + (k0) + akc * 8 \
                                         : g_zero + akc * 8;                   \
        cp16(sb + OFF_A0 + (uint32_t)(buf)*10240u + (uint32_t)(arow * 80 + akc * 16), xsrc); \
        const __half* src0 = g_W1h + (size_t)e * NH * DIM + (k0);              \
        _Pragma("unroll") for (int ii = 0; ii < 2; ii++) {                     \
            int idx = tid + 512 * ii;                                          \
            int n = idx >> 2, kc = idx & 3;                                    \
            cp16(sb + OFF_W + (uint32_t)(buf)*20480u + (uint32_t)(n * 80 + kc * 16), \
                 src0 + (size_t)n * DIM + kc * 8);                             \
        }                                                                      \
        CP_COMMIT();                                                           \
    }
#define CP_WT2(k0, buf)                                                        \
    {                                                                          \
        const __half* src0 = g_W2h + (size_t)e * NH2 * NH + (k0);              \
        {                                                                      \
            int n = tid >> 2, kc = tid & 3;                                    \
            cp16(sb + OFF_W + (uint32_t)(buf)*20480u + (uint32_t)(n * 80 + kc * 16), \
                 src0 + (size_t)n * NH + kc * 8);                              \
        }                                                                      \
        CP_COMMIT();                                                           \
    }

    for (;;) {
        if (tid == 0) s_tile = atomicAdd(&g_next, 1);
        __syncthreads();
        const int tile = s_tile;
        if (tile >= g_ntiles) break;

        const int e = g_tile_head[tile] & (NE - 1);
        const int seg = g_tile_start[tile];
        const int rows = g_tile_rows[tile];
        const bool do_m = (wm * 32) < rows;

        // ---- prologue ----
        if (tid < 128) {
            int tok = -1;
            if (tid < rows) {
                tok = g_tokidx[seg + tid];
                if (tok < 0 || tok >= N_TOK) tok = -1;
            }
            sTok[tid] = tok;
        }
        if (tid >= 192 && tid < 256) {
            int i4 = tid - 192;
            float4 a = ((const float4*)(b1 + (size_t)e * NH))[i4];
            float4 b = ((const float4*)(g_b1p + (size_t)e * NH))[i4];
            ((float4*)sB1)[i4] = make_float4(a.x + b.x, a.y + b.y, a.z + b.z, a.w + b.w);
        }
        if (tid >= 256 && tid < 288)
            ((float4*)sB2)[tid - 256] = ((const float4*)(b2 + (size_t)e * NH2))[tid - 256];
        if (tid >= 288 && tid < 416) {
            int k = tid - 288;
            const float* w3e = W3 + (size_t)e * (NH2 * NO);
            sW3T[k] = w3e[k * 2 + 0];
            sW3T[128 + k] = w3e[k * 2 + 1];
        }
        __syncthreads();
        const int tokr = sTok[arow];
        CP_XW1(0, 0);

        // ===================== GEMM1: [128,768] x [768,256], fp16 =====================
        float acc1[2][8][4];
#pragma unroll
        for (int i = 0; i < 2; i++)
#pragma unroll
            for (int j = 0; j < 8; j++)
#pragma unroll
                for (int q = 0; q < 4; q++) acc1[i][j][q] = 0.f;

        const uint32_t* aw0 = (const uint32_t*)(smem + OFF_A0);
        const uint32_t* aw1 = (const uint32_t*)(smem + OFF_A1);

        for (int i = 0; i < DIM / 32; i++) {
            const int cur = i & 1;
            CP_WAIT0();
            __syncthreads();
            if (i < DIM / 32 - 1) CP_XW1(i * 32 + 32, cur ^ 1);
            if (do_m) {
                const uint32_t* aw = cur ? aw1 : aw0;
                const uint32_t* ww = (const uint32_t*)(smem + OFF_W + (uint32_t)cur * 20480u);
#pragma unroll
                for (int s = 0; s < 2; s++) {
                    uint32_t afr[2][4];
#pragma unroll
                    for (int m = 0; m < 2; m++) {
                        int bidx = (wm * 32 + m * 16 + g) * LDAW + s * 8 + t4;
                        afr[m][0] = aw[bidx];
                        afr[m][1] = aw[bidx + 8 * LDAW];
                        afr[m][2] = aw[bidx + 4];
                        afr[m][3] = aw[bidx + 8 * LDAW + 4];
                    }
#pragma unroll
                    for (int j = 0; j < 8; j++) {
                        int c = wn * 64 + j * 8 + g;
                        uint32_t bfr[2];
                        bfr[0] = ww[c * LDWW + s * 8 + t4];
                        bfr[1] = ww[c * LDWW + s * 8 + t4 + 4];
                        mma_f16(acc1[0][j], afr[0], bfr);
                        mma_f16(acc1[1][j], afr[1], bfr);
                    }
                }
            }
        }
        CP_WT2(0, 0);

        // ---- epilogue1: acc1 + b1', ReLU -> sH1 ----
        if (do_m) {
#pragma unroll
            for (int m = 0; m < 2; m++) {
                int r0 = wm * 32 + m * 16 + g;
#pragma unroll
                for (int j = 0; j < 8; j++) {
                    int c = wn * 64 + j * 8 + 2 * t4;
                    float bx = sB1[c], by = sB1[c + 1];
                    sH1w[r0 * LDH1W + (c >> 1)] =
                        h2u(__floats2half2_rn(fmaxf(acc1[m][j][0] + bx, 0.f),
                                              fmaxf(acc1[m][j][1] + by, 0.f)));
                    sH1w[(r0 + 8) * LDH1W + (c >> 1)] =
                        h2u(__floats2half2_rn(fmaxf(acc1[m][j][2] + bx, 0.f),
                                              fmaxf(acc1[m][j][3] + by, 0.f)));
                }
            }
        }

        // ===================== GEMM2: [128,256] x [256,128], fp16 =====================
        float acc2[2][4][4];
#pragma unroll
        for (int i = 0; i < 2; i++)
#pragma unroll
            for (int j = 0; j < 4; j++)
#pragma unroll
                for (int q = 0; q < 4; q++) acc2[i][j][q] = 0.f;

        for (int i = 0; i < NH / 32; i++) {
            const int cur = i & 1;
            CP_WAIT0();
            __syncthreads();
            if (i < NH / 32 - 1) CP_WT2(i * 32 + 32, cur ^ 1);
            if (do_m) {
                const uint32_t* ww = (const uint32_t*)(smem + OFF_W + (uint32_t)cur * 20480u);
#pragma unroll
                for (int s = 0; s < 2; s++) {
                    uint32_t afr[2][4];
#pragma unroll
                    for (int m = 0; m < 2; m++) {
                        int bidx = (wm * 32 + m * 16 + g) * LDH1W + i * 16 + s * 8 + t4;
                        afr[m][0] = sH1w[bidx];
                        afr[m][1] = sH1w[bidx + 8 * LDH1W];
                        afr[m][2] = sH1w[bidx + 4];
                        afr[m][3] = sH1w[bidx + 8 * LDH1W + 4];
                    }
#pragma unroll
                    for (int j = 0; j < 4; j++) {
                        int c = wn * 32 + j * 8 + g;
                        uint32_t bfr[2];
                        bfr[0] = ww[c * LDWW + s * 8 + t4];
                        bfr[1] = ww[c * LDWW + s * 8 + t4 + 4];
                        mma_f16(acc2[0][j], afr[0], bfr);
                        mma_f16(acc2[1][j], afr[1], bfr);
                    }
                }
            }
        }
        __syncthreads();

        // ---- epilogue2: acc2 + b2, ReLU -> sH2 f32 ----
        if (do_m) {
#pragma unroll
            for (int m = 0; m < 2; m++) {
                int r0 = wm * 32 + m * 16 + g;
#pragma unroll
                for (int j = 0; j < 4; j++) {
                    int c = wn * 32 + j * 8 + 2 * t4;
                    float bx = sB2[c], by = sB2[c + 1];
                    *(float2*)&sH2[r0 * LDH2F + c] =
                        make_float2(fmaxf(acc2[m][j][0] + bx, 0.f), fmaxf(acc2[m][j][1] + by, 0.f));
                    *(float2*)&sH2[(r0 + 8) * LDH2F + c] =
                        make_float2(fmaxf(acc2[m][j][2] + bx, 0.f), fmaxf(acc2[m][j][3] + by, 0.f));
                }
            }
        }
        __syncthreads();

        // ---- GEMM3 + residual epilogue ----
        if (tid < 256) {
            int r = tid >> 1, c = tid & 1;
            if (r < rows) {
                int gt = sTok[r];
                if (gt >= 0) {
                    const float4* h4 = (const float4*)&sH2[r * LDH2F];
                    const float4* w4 = (const float4*)&sW3T[c * 128];
                    float s = 0.f;
#pragma unroll
                    for (int k = 0; k < 32; k++) {
                        float4 a = h4[k], b = w4[k];
                        s += a.x * b.x + a.y * b.y + a.z * b.z + a.w * b.w;
                    }
                    float o = 0.7f * (s + b3[(size_t)e * NO + c]) +
                              0.3f * base[(size_t)gt * NO + c];
                    out[(size_t)gt * NO + c] = o;
                }
            }
        }
        __syncthreads();
    }
}

// ---------------- launcher: exactly 4 launches; k_main is launch #4 ----------------
extern "C" void kernel_launch(void* const* d_in, const int* in_sizes, int n_in,
                              void* d_out, int out_size) {
    const float* hidden = (const float*)d_in[0];
    const float* base = (const float*)d_in[1];
    const void* props = d_in[2];
    const float* mask = (const float*)d_in[3];
    const float* ln_g = (const float*)d_in[4];
    const float* ln_b = (const float*)d_in[5];
    const float* W1 = (const float*)d_in[6];
    const float* b1 = (const float*)d_in[7];
    const float* W2 = (const float*)d_in[8];
    const float* b2 = (const float*)d_in[9];
    const float* W3 = (const float*)d_in[10];
    const float* b3 = (const float*)d_in[11];
    float* out = (float*)d_out;

    cudaFuncSetAttribute(k_main, cudaFuncAttributeMaxDynamicSharedMemorySize, SMEM_BYTES);

    k_prep<<<dim3(12, 64), dim3(32, 8)>>>(W1, W2, ln_g, ln_b, (const unsigned*)props);
    k_stats<<<N_TOK / 8, 256>>>(hidden, props, mask, out);
    k_plan<<<1, 32>>>();
    k_main<<<152, 512, SMEM_BYTES>>>(base, b1, b2, W3, b3, out);
}